// round 10
// baseline (speedup 1.0000x reference)
#include <cuda_runtime.h>
#include <math.h>

// Problem constants
#define Bq   2
#define Lq   2048
#define Eq   1024
#define Hh   16
#define DKd  64
#define DVd  64
#define TOPK 64
#define SCALE_OVER_TEMP 0.15625f
// Posterior blend ramp FULL width -- DO NOT CHANGE
#define TIE_W 1.0e-6f
#define CCAP 96
// fused geometry
#define FROWS 16
#define FCT   256

#define OUT_ELEMS  (Bq * Lq * DVd)
#define ATTN_ELEMS ((size_t)Bq * Hh * Lq * (size_t)Lq)
#define NROWS      (Bq * Hh * Lq)

__device__ float g_qp[Bq * Hh * Lq * DKd];
__device__ float g_kp[Bq * Hh * Lq * DKd];
__device__ float g_vp[Bq * Hh * Lq * DVd];
__device__ float g_mixed[Bq * Lq * Hh * DVd];
__device__ int   g_cidx[(size_t)NROWS * CCAP];
__device__ float g_cval[(size_t)NROWS * CCAP];
__device__ int   g_ccnt[NROWS];
__device__ float g_attn_scratch[Bq * Hh * Lq * Lq];

__device__ __forceinline__ unsigned okey(float f)
{
    unsigned b = __float_as_uint(f);
    return (b & 0x80000000u) ? ~b : (b | 0x80000000u);
}

// -------------------------------------------------------------------------
// proj GEMM: unchanged from R9 (chunked-Kahan, double-buffered).
// -------------------------------------------------------------------------
__global__ void proj_gemm(const float* __restrict__ A, const float* __restrict__ W,
                          float* __restrict__ out, int M, int K, int N,
                          int Lrows, int D)
{
    __shared__ float As[2][16][64];
    __shared__ float Ws[2][16][64];
    const int t  = threadIdx.x;
    const int tx = t & 15, ty = t >> 4;
    const int m0 = blockIdx.y * 64, n0 = blockIdx.x * 64;

    int aM[4], aK[4], wK[4], wN[4];
    #pragma unroll
    for (int i = 0; i < 4; ++i) {
        int idx = t + i * 256;
        aM[i] = idx >> 4; aK[i] = idx & 15;
        wK[i] = idx >> 6; wN[i] = idx & 63;
    }

    float acc[4][4] = {};
    float cmp[4][4] = {};

    float aR[4], wR[4];
    #pragma unroll
    for (int i = 0; i < 4; ++i) {
        aR[i] = A[(size_t)(m0 + aM[i]) * K + aK[i]];
        wR[i] = W[(size_t)wK[i] * N + (n0 + wN[i])];
    }

    const int nc = K >> 4;
    int b = 0;
    for (int c = 0; c < nc; ++c) {
        #pragma unroll
        for (int i = 0; i < 4; ++i) {
            As[b][aK[i]][aM[i]] = aR[i];
            Ws[b][wK[i]][wN[i]] = wR[i];
        }
        __syncthreads();

        if (c + 1 < nc) {
            int k0 = (c + 1) << 4;
            #pragma unroll
            for (int i = 0; i < 4; ++i) {
                aR[i] = A[(size_t)(m0 + aM[i]) * K + (k0 + aK[i])];
                wR[i] = W[(size_t)(k0 + wK[i]) * N + (n0 + wN[i])];
            }
        }

        float part[4][4] = {};
        #pragma unroll
        for (int kk = 0; kk < 16; ++kk) {
            float4 a4 = *(const float4*)&As[b][kk][ty * 4];
            float4 b4 = *(const float4*)&Ws[b][kk][tx * 4];
            float av[4] = {a4.x, a4.y, a4.z, a4.w};
            float bv[4] = {b4.x, b4.y, b4.z, b4.w};
            #pragma unroll
            for (int i = 0; i < 4; ++i)
                #pragma unroll
                for (int j = 0; j < 4; ++j)
                    part[i][j] += av[i] * bv[j];
        }
        #pragma unroll
        for (int i = 0; i < 4; ++i)
            #pragma unroll
            for (int j = 0; j < 4; ++j) {
                float y = part[i][j] - cmp[i][j];
                float s = acc[i][j] + y;
                cmp[i][j] = (s - acc[i][j]) - y;
                acc[i][j] = s;
            }
        b ^= 1;
    }

    const int Hn = N / D;
    #pragma unroll
    for (int i = 0; i < 4; ++i) {
        int m = m0 + ty * 4 + i;
        int bb = m / Lrows, l = m % Lrows;
        #pragma unroll
        for (int j = 0; j < 4; ++j) {
            int n = n0 + tx * 4 + j;
            int h = n / D, dd = n % D;
            out[(((size_t)bb * Hn + h) * Lrows + l) * D + dd] = acc[i][j];
        }
    }
}

// -------------------------------------------------------------------------
// FUSED logits + top-k + softmax + compaction. Block: 16 rows x 2048 cols of
// one z; 256 threads; 4x4 micro-tile over 16x256 column tiles (same FMA:LDS
// ratio as the 89%-of-peak logits_kernel). Logits never touch gmem.
// Per-element Kahan chain identical to R9. Phase 2 = R8/R9-proven warp-local
// radix select + blend + ascending compaction.
// -------------------------------------------------------------------------
__global__ void fused_logits_topk_kernel(const float* __restrict__ qp,
                                         const float* __restrict__ kp,
                                         float* __restrict__ attn,
                                         int* __restrict__ cidx,
                                         float* __restrict__ cval,
                                         int* __restrict__ ccnt)
{
    extern __shared__ float sm[];
    float* sLog = sm;                         // FROWS * 2048
    float* Ks   = sm + FROWS * 2048;          // 64 * 260
    float* Qs   = Ks + 64 * 260;              // FROWS * 68
    unsigned* hist = (unsigned*)Ks;           // aliased in phase 2

    const int t    = threadIdx.x;
    const int lane = t & 31, wid = t >> 5;
    const int z    = blockIdx.y;
    const int row0 = blockIdx.x * FROWS;
    const float* qb = qp + (size_t)z * Lq * DKd;
    const float* kb = kp + (size_t)z * Lq * DKd;

    for (int i = t; i < FROWS * 64; i += 256) {
        int r = i >> 6, kk = i & 63;
        Qs[r * 68 + kk] = qb[(size_t)(row0 + r) * 64 + kk];
    }
    __syncthreads();

    const int tx = t & 63;        // col group (4 cols)
    const int ty = t >> 6;        // row group (4 rows)

    // ---- GEMM phase: 8 column tiles of 256 ----
    for (int ct = 0; ct < Lq / FCT; ++ct) {
        const int n0 = ct * FCT;
        for (int i = t; i < FCT * 16; i += 256) {
            int col = i >> 4, kq = i & 15;
            float4 v = *(const float4*)&kb[((size_t)(n0 + col)) * 64 + kq * 4];
            Ks[(kq * 4 + 0) * 260 + col] = v.x;
            Ks[(kq * 4 + 1) * 260 + col] = v.y;
            Ks[(kq * 4 + 2) * 260 + col] = v.z;
            Ks[(kq * 4 + 3) * 260 + col] = v.w;
        }
        __syncthreads();

        float acc[4][4] = {};
        float cmp[4][4] = {};
        #pragma unroll
        for (int c0 = 0; c0 < 64; c0 += 8) {
            float part[4][4] = {};
            #pragma unroll
            for (int kk = c0; kk < c0 + 8; ++kk) {
                float av[4];
                #pragma unroll
                for (int i = 0; i < 4; ++i) av[i] = Qs[(ty * 4 + i) * 68 + kk];
                float4 b4 = *(const float4*)&Ks[kk * 260 + tx * 4];
                float bv[4] = {b4.x, b4.y, b4.z, b4.w};
                #pragma unroll
                for (int i = 0; i < 4; ++i)
                    #pragma unroll
                    for (int j = 0; j < 4; ++j)
                        part[i][j] += av[i] * bv[j];
            }
            #pragma unroll
            for (int i = 0; i < 4; ++i)
                #pragma unroll
                for (int j = 0; j < 4; ++j) {
                    float y = part[i][j] - cmp[i][j];
                    float s = acc[i][j] + y;
                    cmp[i][j] = (s - acc[i][j]) - y;
                    acc[i][j] = s;
                }
        }
        #pragma unroll
        for (int i = 0; i < 4; ++i) {
            float4 o;
            o.x = acc[i][0] * SCALE_OVER_TEMP;
            o.y = acc[i][1] * SCALE_OVER_TEMP;
            o.z = acc[i][2] * SCALE_OVER_TEMP;
            o.w = acc[i][3] * SCALE_OVER_TEMP;
            *(float4*)&sLog[(ty * 4 + i) * 2048 + n0 + tx * 4] = o;
        }
        __syncthreads();
    }

    // ---- Phase 2: each warp processes rows 2*wid and 2*wid+1 ----
    for (int rr2 = 0; rr2 < 2; ++rr2) {
        const int r = wid * 2 + rr2;
        float* Lrow = &sLog[r * 2048];
        unsigned* myh = hist + wid * 264;
        const size_t grow = (size_t)z * Lq + row0 + r;
        float* arow = attn + grow * Lq;

        unsigned prefix = 0u; int rrk = TOPK;
        for (int s = 24; s >= 0; s -= 8) {
            __syncwarp();
            for (int b = lane; b < 256; b += 32) myh[b] = 0u;
            __syncwarp();
            const unsigned hi = (s == 24) ? 0u : (0xFFFFFFFFu << (s + 8));
            for (int j = 0; j < 64; ++j) {
                unsigned u = okey(Lrow[j * 32 + lane]);
                if (((u ^ prefix) & hi) == 0u)
                    atomicAdd(&myh[(u >> s) & 255u], 1u);
            }
            __syncwarp();
            unsigned h[8]; unsigned s8 = 0u;
            #pragma unroll
            for (int q = 0; q < 8; ++q) { h[q] = myh[lane * 8 + q]; s8 += h[q]; }
            unsigned rs = s8;
            #pragma unroll
            for (int off = 1; off < 32; off <<= 1) {
                unsigned tmp = __shfl_down_sync(0xffffffffu, rs, off);
                rs += (lane + off < 32) ? tmp : 0u;
            }
            unsigned above = __shfl_down_sync(0xffffffffu, rs, 1);
            if (lane == 31) above = 0u;
            unsigned cum = above;
            int fdig = -1, frr = 0;
            #pragma unroll
            for (int q = 7; q >= 0; --q) {
                unsigned c = h[q];
                if (fdig < 0 && cum < (unsigned)rrk && cum + c >= (unsigned)rrk) {
                    fdig = lane * 8 + q; frr = rrk - (int)cum;
                }
                cum += c;
            }
            unsigned bal = __ballot_sync(0xffffffffu, fdig >= 0);
            int src = __ffs((int)bal) - 1;
            fdig = __shfl_sync(0xffffffffu, fdig, src);
            frr  = __shfl_sync(0xffffffffu, frr,  src);
            prefix |= ((unsigned)fdig) << s;
            rrk = frr;
        }
        const unsigned ukth = prefix;

        float mx = -3.0e38f, l64 = -3.0e38f, l65 = -3.0e38f;
        for (int j = 0; j < 64; ++j) {
            float v = Lrow[j * 32 + lane];
            unsigned u = okey(v);
            mx = fmaxf(mx, v);
            if (u == ukth) l64 = fmaxf(l64, v);
            if (u <  ukth) l65 = fmaxf(l65, v);
        }
        #pragma unroll
        for (int off = 16; off > 0; off >>= 1) {
            mx  = fmaxf(mx,  __shfl_xor_sync(0xffffffffu, mx,  off));
            l64 = fmaxf(l64, __shfl_xor_sync(0xffffffffu, l64, off));
            l65 = fmaxf(l65, __shfl_xor_sync(0xffffffffu, l65, off));
        }
        const float mu = 0.5f * (l64 + l65);

        // single exp pass: store unnormalized e back into sLog
        float sum = 0.0f;
        for (int j = 0; j < 64; ++j) {
            float v = Lrow[j * 32 + lane];
            float w = __saturatef((v - mu) * (1.0f / TIE_W) + 0.5f);
            float e = (w > 0.0f) ? w * expf(v - mx) : 0.0f;
            sum += e;
            Lrow[j * 32 + lane] = e;
        }
        #pragma unroll
        for (int off = 16; off > 0; off >>= 1)
            sum += __shfl_xor_sync(0xffffffffu, sum, off);
        const float inv = 1.0f / sum;

        int base = 0;
        int*   ci = cidx + grow * CCAP;
        float* cv = cval + grow * CCAP;
        for (int j = 0; j < 64; ++j) {
            float e = Lrow[j * 32 + lane];
            float av = e * inv;
            arow[j * 32 + lane] = av;
            unsigned bal = __ballot_sync(0xffffffffu, e > 0.0f);
            if (e > 0.0f) {
                int pos = base + __popc(bal & ((1u << lane) - 1u));
                if (pos < CCAP) { ci[pos] = j * 32 + lane; cv[pos] = av; }
            }
            base += __popc(bal);
        }
        if (lane == 0) ccnt[grow] = (base < CCAP) ? base : CCAP;
    }
}

// -------------------------------------------------------------------------
// Sparse mixed (unchanged): ascending sparse sum == dense sequential bitwise.
// -------------------------------------------------------------------------
__global__ void mixed_sparse_kernel(const int* __restrict__ cidx,
                                    const float* __restrict__ cval,
                                    const int* __restrict__ ccnt,
                                    const float* __restrict__ vp)
{
    const int lane = threadIdx.x & 31;
    const int gw   = blockIdx.x * 8 + (threadIdx.x >> 5);
    const int z = gw >> 11, l = gw & 2047;
    const float* vb = vp + (size_t)z * Lq * DVd;
    const int cnt = ccnt[gw];
    const int*   ci = cidx + (size_t)gw * CCAP;
    const float* cv = cval + (size_t)gw * CCAP;

    float a0 = 0.0f, a1 = 0.0f;
    int kk = 0;
    for (; kk + 4 <= cnt; kk += 4) {
        #pragma unroll
        for (int u = 0; u < 4; ++u) {
            int   id = ci[kk + u];
            float w  = cv[kk + u];
            const float* vr = vb + (size_t)id * DVd;
            a0 = __fmaf_rn(w, vr[lane], a0);
            a1 = __fmaf_rn(w, vr[32 + lane], a1);
        }
    }
    for (; kk < cnt; ++kk) {
        int   id = ci[kk];
        float w  = cv[kk];
        const float* vr = vb + (size_t)id * DVd;
        a0 = __fmaf_rn(w, vr[lane], a0);
        a1 = __fmaf_rn(w, vr[32 + lane], a1);
    }

    const int b = z >> 4, h = z & 15;
    float* dst = g_mixed + ((size_t)(b * Lq + l)) * (Hh * DVd) + h * DVd;
    dst[lane]      = a0;
    dst[32 + lane] = a1;
}

extern "C" void kernel_launch(void* const* d_in, const int* in_sizes, int n_in,
                              void* d_out, int out_size)
{
    const float* q    = (const float*)d_in[0];
    const float* k    = (const float*)d_in[1];
    const float* v    = (const float*)d_in[2];
    const float* w_qs = (const float*)d_in[3];
    const float* w_ks = (const float*)d_in[4];
    const float* w_vs = (const float*)d_in[5];
    const float* fc   = (const float*)d_in[6];
    float* out = (float*)d_out;

    float *qp, *kp, *vp, *mixed, *attn, *cval;
    int *cidx, *ccnt;
    { void* p; cudaGetSymbolAddress(&p, g_qp);    qp    = (float*)p; }
    { void* p; cudaGetSymbolAddress(&p, g_kp);    kp    = (float*)p; }
    { void* p; cudaGetSymbolAddress(&p, g_vp);    vp    = (float*)p; }
    { void* p; cudaGetSymbolAddress(&p, g_mixed); mixed = (float*)p; }
    { void* p; cudaGetSymbolAddress(&p, g_cidx);  cidx  = (int*)p; }
    { void* p; cudaGetSymbolAddress(&p, g_cval);  cval  = (float*)p; }
    { void* p; cudaGetSymbolAddress(&p, g_ccnt);  ccnt  = (int*)p; }
    if ((size_t)out_size >= (size_t)OUT_ELEMS + ATTN_ELEMS) {
        attn = out + OUT_ELEMS;
    } else {
        void* p; cudaGetSymbolAddress(&p, g_attn_scratch); attn = (float*)p;
    }

    const dim3 thr(256);
    const int M = Bq * Lq;

    proj_gemm<<<dim3(Eq / 64, M / 64), thr>>>(q, w_qs, qp, M, Eq, Hh * DKd, Lq, DKd);
    proj_gemm<<<dim3(Eq / 64, M / 64), thr>>>(k, w_ks, kp, M, Eq, Hh * DKd, Lq, DKd);
    proj_gemm<<<dim3(Eq / 64, M / 64), thr>>>(v, w_vs, vp, M, DVd, Hh * DVd, Lq, DVd);

    // Fused logits + top-k + softmax + compaction (attn written once)
    const int fused_smem = (FROWS * 2048 + 64 * 260 + FROWS * 68) * (int)sizeof(float);
    cudaFuncSetAttribute(fused_logits_topk_kernel,
                         cudaFuncAttributeMaxDynamicSharedMemorySize, fused_smem);
    fused_logits_topk_kernel<<<dim3(Lq / FROWS, Bq * Hh), thr, fused_smem>>>(
        qp, kp, attn, cidx, cval, ccnt);

    mixed_sparse_kernel<<<dim3(NROWS / 8), thr>>>(cidx, cval, ccnt, vp);

    proj_gemm<<<dim3(1, M / 64), thr>>>(mixed, fc, out, M, Hh * DVd, DVd, M, DVd);
}

// round 11
// speedup vs baseline: 1.5380x; 1.5380x over previous
#include <cuda_runtime.h>
#include <math.h>

// Problem constants
#define Bq   2
#define Lq   2048
#define Eq   1024
#define Hh   16
#define DKd  64
#define DVd  64
#define TOPK 64
#define SCALE_OVER_TEMP 0.15625f
// Posterior blend ramp FULL width -- DO NOT CHANGE
#define TIE_W 1.0e-6f
#define CCAP 96

#define OUT_ELEMS  (Bq * Lq * DVd)
#define ATTN_ELEMS ((size_t)Bq * Hh * Lq * (size_t)Lq)
#define NROWS      (Bq * Hh * Lq)

__device__ float g_qp[Bq * Hh * Lq * DKd];
__device__ float g_kp[Bq * Hh * Lq * DKd];
__device__ float g_vp[Bq * Hh * Lq * DVd];
__device__ float g_mixed[Bq * Lq * Hh * DVd];
__device__ int   g_cidx[(size_t)NROWS * CCAP];
__device__ float g_cval[(size_t)NROWS * CCAP];
__device__ int   g_ccnt[NROWS];
__device__ float g_attn_scratch[Bq * Hh * Lq * Lq];

__device__ __forceinline__ unsigned okey(float f)
{
    unsigned b = __float_as_uint(f);
    return (b & 0x80000000u) ? ~b : (b | 0x80000000u);
}

// -------------------------------------------------------------------------
// proj GEMM: unchanged from R9 (chunked-Kahan, double-buffered).
// -------------------------------------------------------------------------
__global__ void proj_gemm(const float* __restrict__ A, const float* __restrict__ W,
                          float* __restrict__ out, int M, int K, int N,
                          int Lrows, int D)
{
    __shared__ float As[2][16][64];
    __shared__ float Ws[2][16][64];
    const int t  = threadIdx.x;
    const int tx = t & 15, ty = t >> 4;
    const int m0 = blockIdx.y * 64, n0 = blockIdx.x * 64;

    int aM[4], aK[4], wK[4], wN[4];
    #pragma unroll
    for (int i = 0; i < 4; ++i) {
        int idx = t + i * 256;
        aM[i] = idx >> 4; aK[i] = idx & 15;
        wK[i] = idx >> 6; wN[i] = idx & 63;
    }

    float acc[4][4] = {};
    float cmp[4][4] = {};

    float aR[4], wR[4];
    #pragma unroll
    for (int i = 0; i < 4; ++i) {
        aR[i] = A[(size_t)(m0 + aM[i]) * K + aK[i]];
        wR[i] = W[(size_t)wK[i] * N + (n0 + wN[i])];
    }

    const int nc = K >> 4;
    int b = 0;
    for (int c = 0; c < nc; ++c) {
        #pragma unroll
        for (int i = 0; i < 4; ++i) {
            As[b][aK[i]][aM[i]] = aR[i];
            Ws[b][wK[i]][wN[i]] = wR[i];
        }
        __syncthreads();

        if (c + 1 < nc) {
            int k0 = (c + 1) << 4;
            #pragma unroll
            for (int i = 0; i < 4; ++i) {
                aR[i] = A[(size_t)(m0 + aM[i]) * K + (k0 + aK[i])];
                wR[i] = W[(size_t)(k0 + wK[i]) * N + (n0 + wN[i])];
            }
        }

        float part[4][4] = {};
        #pragma unroll
        for (int kk = 0; kk < 16; ++kk) {
            float4 a4 = *(const float4*)&As[b][kk][ty * 4];
            float4 b4 = *(const float4*)&Ws[b][kk][tx * 4];
            float av[4] = {a4.x, a4.y, a4.z, a4.w};
            float bv[4] = {b4.x, b4.y, b4.z, b4.w};
            #pragma unroll
            for (int i = 0; i < 4; ++i)
                #pragma unroll
                for (int j = 0; j < 4; ++j)
                    part[i][j] += av[i] * bv[j];
        }
        #pragma unroll
        for (int i = 0; i < 4; ++i)
            #pragma unroll
            for (int j = 0; j < 4; ++j) {
                float y = part[i][j] - cmp[i][j];
                float s = acc[i][j] + y;
                cmp[i][j] = (s - acc[i][j]) - y;
                acc[i][j] = s;
            }
        b ^= 1;
    }

    const int Hn = N / D;
    #pragma unroll
    for (int i = 0; i < 4; ++i) {
        int m = m0 + ty * 4 + i;
        int bb = m / Lrows, l = m % Lrows;
        #pragma unroll
        for (int j = 0; j < 4; ++j) {
            int n = n0 + tx * 4 + j;
            int h = n / D, dd = n % D;
            out[(((size_t)bb * Hn + h) * Lrows + l) * D + dd] = acc[i][j];
        }
    }
}

// -------------------------------------------------------------------------
// logits: unchanged from R9 (chunked-Kahan, k-major smem).
// -------------------------------------------------------------------------
__global__ void logits_kernel(const float* __restrict__ qp, const float* __restrict__ kp,
                              float* __restrict__ attn)
{
    __shared__ float Qs[64][68];
    __shared__ float Ks[64][68];
    const int t  = threadIdx.x;
    const int tx = t & 15, ty = t >> 4;
    const int z  = blockIdx.z;
    const int m0 = blockIdx.y * 64, n0 = blockIdx.x * 64;
    const float* qb = qp + (size_t)z * Lq * DKd;
    const float* kb = kp + (size_t)z * Lq * DKd;

    #pragma unroll
    for (int i = 0; i < 16; ++i) {
        int idx = t + i * 256;
        int r = idx >> 6, c = idx & 63;
        Qs[c][r] = qb[(size_t)(m0 + r) * DKd + c];
        Ks[c][r] = kb[(size_t)(n0 + r) * DKd + c];
    }
    __syncthreads();

    float acc[4][4] = {};
    float cmp[4][4] = {};
    #pragma unroll
    for (int c0 = 0; c0 < 64; c0 += 8) {
        float part[4][4] = {};
        #pragma unroll
        for (int kk = c0; kk < c0 + 8; ++kk) {
            float4 a4 = *(const float4*)&Qs[kk][ty * 4];
            float4 b4 = *(const float4*)&Ks[kk][tx * 4];
            float av[4] = {a4.x, a4.y, a4.z, a4.w};
            float bv[4] = {b4.x, b4.y, b4.z, b4.w};
            #pragma unroll
            for (int i = 0; i < 4; ++i)
                #pragma unroll
                for (int j = 0; j < 4; ++j)
                    part[i][j] += av[i] * bv[j];
        }
        #pragma unroll
        for (int i = 0; i < 4; ++i)
            #pragma unroll
            for (int j = 0; j < 4; ++j) {
                float y = part[i][j] - cmp[i][j];
                float s = acc[i][j] + y;
                cmp[i][j] = (s - acc[i][j]) - y;
                acc[i][j] = s;
            }
    }

    float* arow = attn + (size_t)z * Lq * Lq;
    #pragma unroll
    for (int i = 0; i < 4; ++i) {
        int m = m0 + ty * 4 + i;
        #pragma unroll
        for (int j = 0; j < 4; ++j) {
            int n = n0 + tx * 4 + j;
            arow[(size_t)m * Lq + n] = acc[i][j] * SCALE_OVER_TEMP;
        }
    }
}

// -------------------------------------------------------------------------
// Per-row exact top-k + blended softmax + compaction.
// Same selection math as R9 (cached keys; counts/select identical).
// NEW: compact (idx, raw v) first with the bit-identical w>0 test, then
// expf ONLY on the ~64 compacted entries (32x fewer expf), zero-fill +
// scatter for the dense attn row. Normalizer sum order changes (<=1ulp on
// inv; selection already fixed by then -- non-flip-critical).
// -------------------------------------------------------------------------
__global__ void topk_softmax_kernel(float* __restrict__ attn,
                                    int* __restrict__ cidx,
                                    float* __restrict__ cval,
                                    int* __restrict__ ccnt)
{
    __shared__ unsigned hist[256];
    __shared__ unsigned s_prefix;
    __shared__ int      s_r;
    __shared__ float    redf[24];
    __shared__ float    s_scal[3];
    __shared__ int      warpCnt[64];
    __shared__ int      warpOff[64];
    __shared__ int      s_cnt;
    __shared__ int      sIdxC[2048];
    __shared__ float    sValC[2048];

    const int t = threadIdx.x;
    const int wid = t >> 5, lane = t & 31;
    const size_t row_id = blockIdx.x;
    float* row = attn + row_id * Lq;

    float local[8];
    unsigned key[8];
    #pragma unroll
    for (int i = 0; i < 8; ++i) {
        local[i] = row[t + i * 256];
        key[i]   = okey(local[i]);
    }

    if (t == 0) { s_r = TOPK; s_prefix = 0u; }
    __syncthreads();

    // 4-pass radix select (counts + warp0 suffix-scan select, as R9)
    for (int s = 24; s >= 0; s -= 8) {
        hist[t] = 0u;
        __syncthreads();
        const unsigned hi_mask = (s == 24) ? 0u : (0xFFFFFFFFu << (s + 8));
        const unsigned prefix  = s_prefix;
        const int      rr      = s_r;
        #pragma unroll
        for (int i = 0; i < 8; ++i) {
            if (((key[i] ^ prefix) & hi_mask) == 0u)
                atomicAdd(&hist[(key[i] >> s) & 255u], 1u);
        }
        __syncthreads();
        if (wid == 0) {
            unsigned h[8]; unsigned s8 = 0u;
            #pragma unroll
            for (int q = 0; q < 8; ++q) { h[q] = hist[lane * 8 + q]; s8 += h[q]; }
            unsigned rs = s8;
            #pragma unroll
            for (int off = 1; off < 32; off <<= 1) {
                unsigned tmp = __shfl_down_sync(0xffffffffu, rs, off);
                rs += (lane + off < 32) ? tmp : 0u;
            }
            unsigned above = __shfl_down_sync(0xffffffffu, rs, 1);
            if (lane == 31) above = 0u;
            unsigned cum = above;
            int fdig = -1, frr = 0;
            #pragma unroll
            for (int q = 7; q >= 0; --q) {
                unsigned c = h[q];
                if (fdig < 0 && cum < (unsigned)rr && cum + c >= (unsigned)rr) {
                    fdig = lane * 8 + q; frr = rr - (int)cum;
                }
                cum += c;
            }
            unsigned bal = __ballot_sync(0xffffffffu, fdig >= 0);
            int src = __ffs((int)bal) - 1;
            fdig = __shfl_sync(0xffffffffu, fdig, src);
            frr  = __shfl_sync(0xffffffffu, frr,  src);
            if (lane == 0) {
                s_prefix = prefix | ((unsigned)fdig << s);
                s_r = frr;
            }
        }
        __syncthreads();
    }
    const unsigned ukth = s_prefix;

    // m (row max), L64, L65
    float l64 = -3.0e38f, l65 = -3.0e38f, m = -3.0e38f;
    #pragma unroll
    for (int i = 0; i < 8; ++i) {
        m = fmaxf(m, local[i]);
        if (key[i] == ukth) l64 = fmaxf(l64, local[i]);
        if (key[i] <  ukth) l65 = fmaxf(l65, local[i]);
    }
    #pragma unroll
    for (int o = 16; o > 0; o >>= 1) {
        m   = fmaxf(m,   __shfl_xor_sync(0xffffffffu, m,   o));
        l64 = fmaxf(l64, __shfl_xor_sync(0xffffffffu, l64, o));
        l65 = fmaxf(l65, __shfl_xor_sync(0xffffffffu, l65, o));
    }
    if (lane == 0) { redf[wid] = m; redf[8 + wid] = l64; redf[16 + wid] = l65; }
    __syncthreads();
    if (t == 0) {
        float mm = redf[0], a = redf[8], bmax = redf[16];
        #pragma unroll
        for (int w = 1; w < 8; ++w) {
            mm   = fmaxf(mm,   redf[w]);
            a    = fmaxf(a,    redf[8 + w]);
            bmax = fmaxf(bmax, redf[16 + w]);
        }
        s_scal[0] = mm;
        s_scal[1] = 0.5f * (a + bmax);   // mu
    }
    __syncthreads();
    m = s_scal[0];
    const float mu = s_scal[1];

    // zero-fill dense row (all local[] already in registers block-wide)
    {
        float4 z4 = make_float4(0.f, 0.f, 0.f, 0.f);
        float4* r4 = (float4*)row;
        r4[t]       = z4;
        r4[t + 256] = z4;
    }

    // compact kept (w > 0, w computed with the IDENTICAL formula)
    unsigned bal[8];
    bool kept[8];
    #pragma unroll
    for (int i = 0; i < 8; ++i) {
        float w = __saturatef((local[i] - mu) * (1.0f / TIE_W) + 0.5f);
        kept[i] = (w > 0.0f);
        bal[i] = __ballot_sync(0xffffffffu, kept[i]);
        if (lane == 0) warpCnt[i * 8 + wid] = __popc(bal[i]);
    }
    __syncthreads();
    if (t == 0) {
        int running = 0;
        for (int j = 0; j < 64; ++j) { warpOff[j] = running; running += warpCnt[j]; }
        s_cnt = running;
        ccnt[row_id] = (running < CCAP) ? running : CCAP;
    }
    __syncthreads();
    #pragma unroll
    for (int i = 0; i < 8; ++i) {
        if (kept[i]) {
            int pos = warpOff[i * 8 + wid] + __popc(bal[i] & ((1u << lane) - 1u));
            sIdxC[pos] = i * 256 + t;     // ascending element index order
            sValC[pos] = local[i];
        }
    }
    __syncthreads();

    // exp ONLY on compacted entries (~64 instead of 2048)
    const int cnt = s_cnt;
    for (int p = t; p < cnt; p += 256) {
        float v = sValC[p];
        float w = __saturatef((v - mu) * (1.0f / TIE_W) + 0.5f);
        sValC[p] = w * expf(v - m);
    }
    __syncthreads();

    // normalizer (warp 0)
    if (wid == 0) {
        float s = 0.0f;
        for (int p = lane; p < cnt; p += 32) s += sValC[p];
        #pragma unroll
        for (int o = 16; o > 0; o >>= 1) s += __shfl_xor_sync(0xffffffffu, s, o);
        if (lane == 0) s_scal[2] = 1.0f / s;
    }
    __syncthreads();
    const float inv = s_scal[2];

    // scatter dense + compact outputs
    for (int p = t; p < cnt; p += 256) {
        float av = sValC[p] * inv;
        int   id = sIdxC[p];
        row[id] = av;
        if (p < CCAP) {
            cidx[row_id * CCAP + p] = id;
            cval[row_id * CCAP + p] = av;
        }
    }
}

// -------------------------------------------------------------------------
// Sparse mixed (unchanged).
// -------------------------------------------------------------------------
__global__ void mixed_sparse_kernel(const int* __restrict__ cidx,
                                    const float* __restrict__ cval,
                                    const int* __restrict__ ccnt,
                                    const float* __restrict__ vp)
{
    const int lane = threadIdx.x & 31;
    const int gw   = blockIdx.x * 8 + (threadIdx.x >> 5);
    const int z = gw >> 11, l = gw & 2047;
    const float* vb = vp + (size_t)z * Lq * DVd;
    const int cnt = ccnt[gw];
    const int*   ci = cidx + (size_t)gw * CCAP;
    const float* cv = cval + (size_t)gw * CCAP;

    float a0 = 0.0f, a1 = 0.0f;
    int kk = 0;
    for (; kk + 4 <= cnt; kk += 4) {
        #pragma unroll
        for (int u = 0; u < 4; ++u) {
            int   id = ci[kk + u];
            float w  = cv[kk + u];
            const float* vr = vb + (size_t)id * DVd;
            a0 = __fmaf_rn(w, vr[lane], a0);
            a1 = __fmaf_rn(w, vr[32 + lane], a1);
        }
    }
    for (; kk < cnt; ++kk) {
        int   id = ci[kk];
        float w  = cv[kk];
        const float* vr = vb + (size_t)id * DVd;
        a0 = __fmaf_rn(w, vr[lane], a0);
        a1 = __fmaf_rn(w, vr[32 + lane], a1);
    }

    const int b = z >> 4, h = z & 15;
    float* dst = g_mixed + ((size_t)(b * Lq + l)) * (Hh * DVd) + h * DVd;
    dst[lane]      = a0;
    dst[32 + lane] = a1;
}

extern "C" void kernel_launch(void* const* d_in, const int* in_sizes, int n_in,
                              void* d_out, int out_size)
{
    const float* q    = (const float*)d_in[0];
    const float* k    = (const float*)d_in[1];
    const float* v    = (const float*)d_in[2];
    const float* w_qs = (const float*)d_in[3];
    const float* w_ks = (const float*)d_in[4];
    const float* w_vs = (const float*)d_in[5];
    const float* fc   = (const float*)d_in[6];
    float* out = (float*)d_out;

    float *qp, *kp, *vp, *mixed, *attn, *cval;
    int *cidx, *ccnt;
    { void* p; cudaGetSymbolAddress(&p, g_qp);    qp    = (float*)p; }
    { void* p; cudaGetSymbolAddress(&p, g_kp);    kp    = (float*)p; }
    { void* p; cudaGetSymbolAddress(&p, g_vp);    vp    = (float*)p; }
    { void* p; cudaGetSymbolAddress(&p, g_mixed); mixed = (float*)p; }
    { void* p; cudaGetSymbolAddress(&p, g_cidx);  cidx  = (int*)p; }
    { void* p; cudaGetSymbolAddress(&p, g_cval);  cval  = (float*)p; }
    { void* p; cudaGetSymbolAddress(&p, g_ccnt);  ccnt  = (int*)p; }
    if ((size_t)out_size >= (size_t)OUT_ELEMS + ATTN_ELEMS) {
        attn = out + OUT_ELEMS;
    } else {
        void* p; cudaGetSymbolAddress(&p, g_attn_scratch); attn = (float*)p;
    }

    const dim3 thr(256);
    const int M = Bq * Lq;

    proj_gemm<<<dim3(Eq / 64, M / 64), thr>>>(q, w_qs, qp, M, Eq, Hh * DKd, Lq, DKd);
    proj_gemm<<<dim3(Eq / 64, M / 64), thr>>>(k, w_ks, kp, M, Eq, Hh * DKd, Lq, DKd);
    proj_gemm<<<dim3(Eq / 64, M / 64), thr>>>(v, w_vs, vp, M, DVd, Hh * DVd, Lq, DVd);

    logits_kernel<<<dim3(Lq / 64, Lq / 64, Bq * Hh), thr>>>(qp, kp, attn);

    topk_softmax_kernel<<<dim3(NROWS), thr>>>(attn, cidx, cval, ccnt);

    mixed_sparse_kernel<<<dim3(NROWS / 8), thr>>>(cidx, cval, ccnt, vp);

    proj_gemm<<<dim3(1, M / 64), thr>>>(mixed, fc, out, M, Hh * DVd, DVd, M, DVd);
}